// round 11
// baseline (speedup 1.0000x reference)
#include <cuda_runtime.h>
#include <cuda_fp16.h>

#define HH 512
#define WW 512
#define OW 506
#define BATCH 32
#define CH 3
#define TX 64
#define TY 32
#define ITY 38          // TY + 6
#define STRH 80         // halves per hs row: 160B row pitch
#define GX 8
#define GY 16
#define NBLOCKS (GX * GY * BATCH * CH)
#define PLANE_B (ITY * STRH * 2)   // bytes per plane = 6080

#define F8 0xFFFFFFFFu
__device__ unsigned g_minBits[BATCH] = {
    F8, F8, F8, F8, F8, F8, F8, F8, F8, F8, F8, F8, F8, F8, F8, F8,
    F8, F8, F8, F8, F8, F8, F8, F8, F8, F8, F8, F8, F8, F8, F8, F8};
__device__ unsigned g_maxBits[BATCH];
__device__ double g_acc;
__device__ unsigned g_done;

// ---------------- packed helpers ----------------
typedef unsigned long long ull;
__device__ __forceinline__ ull rep2(float f) {
    ull r; asm("mov.b64 %0,{%1,%1};" : "=l"(r) : "f"(f)); return r;
}
__device__ __forceinline__ ull add2(ull a, ull b) {
    ull d; asm("add.rn.f32x2 %0,%1,%2;" : "=l"(d) : "l"(a), "l"(b)); return d;
}
__device__ __forceinline__ ull mul2(ull a, ull b) {
    ull d; asm("mul.rn.f32x2 %0,%1,%2;" : "=l"(d) : "l"(a), "l"(b)); return d;
}
__device__ __forceinline__ ull fma2(ull a, ull b, ull c) {
    ull d; asm("fma.rn.f32x2 %0,%1,%2,%3;" : "=l"(d) : "l"(a), "l"(b), "l"(c)); return d;
}
__device__ __forceinline__ void unpk(ull v, float& a, float& b) {
    asm("mov.b64 {%0,%1},%2;" : "=f"(a), "=f"(b) : "l"(v));
}
__device__ __forceinline__ unsigned packh2(float lo, float hi) {
    unsigned r; asm("cvt.rn.f16x2.f32 %0,%1,%2;" : "=r"(r) : "f"(hi), "f"(lo));
    return r;
}
__device__ __forceinline__ ull h2f(unsigned h) {
    ull d;
    asm("{.reg .f16 l,u; .reg .f32 a,b; mov.b32 {l,u},%1;"
        " cvt.f32.f16 a,l; cvt.f32.f16 b,u; mov.b64 %0,{a,b};}"
        : "=l"(d) : "r"(h));
    return d;
}
__device__ __forceinline__ unsigned hadd2u(unsigned a, unsigned b) {
    unsigned d; asm("add.rn.f16x2 %0,%1,%2;" : "=r"(d) : "r"(a), "r"(b)); return d;
}
__device__ __forceinline__ unsigned hsub2u(unsigned a, unsigned b) {
    unsigned d; asm("sub.rn.f16x2 %0,%1,%2;" : "=r"(d) : "r"(a), "r"(b)); return d;
}
__device__ __forceinline__ unsigned lds1(unsigned a) {
    unsigned v; asm volatile("ld.shared.b32 %0,[%1];" : "=r"(v) : "r"(a)); return v;
}
__device__ __forceinline__ void sts4u(unsigned a, uint4 v) {
    asm volatile("st.shared.v4.b32 [%0],{%1,%2,%3,%4};"
                 :: "r"(a), "r"(v.x), "r"(v.y), "r"(v.z), "r"(v.w) : "memory");
}

// Per-image min/max of img2 (values >= 0 -> uint ordering == float ordering).
__global__ void minmax_kernel(const float* __restrict__ img2) {
    int b = blockIdx.x;
    const float4* p = (const float4*)(img2 + (size_t)b * (CH * HH * WW));
    const int n4 = CH * HH * WW / 4;
    const int stride = gridDim.y * blockDim.x;
    unsigned lo = F8, hi = 0u;
    int i = blockIdx.y * blockDim.x + threadIdx.x;
    for (; i + 3 * stride < n4; i += 4 * stride) {
        float4 v0 = p[i];
        float4 v1 = p[i + stride];
        float4 v2 = p[i + 2 * stride];
        float4 v3 = p[i + 3 * stride];
        #define MM(v) { \
            unsigned a0 = __float_as_uint((v).x), a1 = __float_as_uint((v).y); \
            unsigned a2 = __float_as_uint((v).z), a3 = __float_as_uint((v).w); \
            lo = min(lo, min(min(a0, a1), min(a2, a3))); \
            hi = max(hi, max(max(a0, a1), max(a2, a3))); }
        MM(v0) MM(v1) MM(v2) MM(v3)
    }
    for (; i < n4; i += stride) { float4 v = p[i]; MM(v) }
    #undef MM
    #pragma unroll
    for (int o = 16; o; o >>= 1) {
        lo = min(lo, __shfl_down_sync(F8, lo, o));
        hi = max(hi, __shfl_down_sync(F8, hi, o));
    }
    __shared__ unsigned slo[8], shi[8];
    int lane = threadIdx.x & 31, w = threadIdx.x >> 5;
    if (lane == 0) { slo[w] = lo; shi[w] = hi; }
    __syncthreads();
    if (threadIdx.x == 0) {
        #pragma unroll
        for (int k = 1; k < 8; k++) { lo = min(lo, slo[k]); hi = max(hi, shi[k]); }
        atomicMin(&g_minBits[b], lo);
        atomicMax(&g_maxBits[b], hi);
    }
}

// One 64x32 output tile per block. 4 fp16 SMEM planes: sum(x), sum(y),
// sum(x^2+y^2), sum(xy). Row-parity swizzle (+16B on odd rows) keeps both
// STS.128 and stage-B LDS.32 conflict-free. Stage A: 16-col items with
// PHASED float4 loads (1.5x halo instead of 2x) and early per-half STS
// flush to contain register pressure. Stage B: f16x2 ring + packed f32x2
// SSIM epilogue. 5 blocks/SM.
__global__ __launch_bounds__(256, 5) void ssim_kernel(const float* __restrict__ X,
                                                      const float* __restrict__ Y,
                                                      float* __restrict__ out) {
    extern __shared__ char smraw[];
    __shared__ float wsum[8];

    const int z = blockIdx.z;
    const size_t base = (size_t)z * (HH * WW);
    const int x0 = blockIdx.x * TX;
    const int y0 = blockIdx.y * TY;
    const int tid = threadIdx.x, lane = tid & 31, warp = tid >> 5;
    const unsigned sb = (unsigned)__cvta_generic_to_shared(smraw);

    // ---- stage A: horizontal 7-sums, 16 output cols per item ----
    for (int item = tid; item < ITY * 4; item += 256) {
        const int r = item >> 2;
        const int c0 = (item & 3) * 16;
        const int iy = y0 + r;
        const float* px = X + base + (size_t)iy * WW;
        const float* py = Y + base + (size_t)iy * WW;
        const bool yok = iy < HH;

        float ax[24], ay[24];
        #define LD4(k) { \
            const int col = x0 + c0 + 4 * (k); \
            const bool ok = yok && (col <= WW - 4); \
            float4 vx = ok ? *(const float4*)(px + col) : make_float4(0, 0, 0, 0); \
            float4 vy = ok ? *(const float4*)(py + col) : make_float4(0, 0, 0, 0); \
            ax[4 * (k) + 0] = vx.x; ax[4 * (k) + 1] = vx.y; \
            ax[4 * (k) + 2] = vx.z; ax[4 * (k) + 3] = vx.w; \
            ay[4 * (k) + 0] = vy.x; ay[4 * (k) + 1] = vy.y; \
            ay[4 * (k) + 2] = vy.z; ay[4 * (k) + 3] = vy.w; }

        LD4(0) LD4(1) LD4(2)   // cols 0..11

        float s1 = 0.f, s2 = 0.f, s34 = 0.f, s5 = 0.f;
        #pragma unroll
        for (int k = 0; k < 7; k++) {
            s1 += ax[k]; s2 += ay[k];
            s34 += ax[k] * ax[k] + ay[k] * ay[k];
            s5 += ax[k] * ay[k];
        }

        const unsigned rowb = sb + (unsigned)(r * (STRH * 2) + c0 * 2)
                              + ((r & 1) ? 16u : 0u);

        uint4 q1, q2, q34, q5;
        float l1 = s1, l2 = s2, l34 = s34, l5 = s5;
        #pragma unroll
        for (int half = 0; half < 2; half++) {
            #pragma unroll
            for (int jj = (half ? 0 : 1); jj < 8; jj++) {
                const int cc = half * 8 + jj;
                if (cc == 5) LD4(3)        // cols 12..15 first used at cc=6
                if (cc == 9) LD4(4)        // cols 16..19 first used at cc=10
                if (cc == 13) LD4(5)       // cols 20..23 first used at cc=14
                const float xn = ax[6 + cc], yn = ay[6 + cc];
                const float xo = ax[cc - 1], yo = ay[cc - 1];
                s1 += xn - xo;
                s2 += yn - yo;
                s34 += xn * xn + yn * yn - xo * xo - yo * yo;
                s5 += xn * yn - xo * yo;
                if (cc & 1) {
                    const int q = jj >> 1;
                    ((unsigned*)&q1)[q] = packh2(l1, s1);
                    ((unsigned*)&q2)[q] = packh2(l2, s2);
                    ((unsigned*)&q34)[q] = packh2(l34, s34);
                    ((unsigned*)&q5)[q] = packh2(l5, s5);
                } else {
                    l1 = s1; l2 = s2; l34 = s34; l5 = s5;
                }
            }
            const unsigned addr = rowb + (unsigned)(half * 16);
            sts4u(addr + 0u * PLANE_B, q1);
            sts4u(addr + 1u * PLANE_B, q2);
            sts4u(addr + 2u * PLANE_B, q34);
            sts4u(addr + 3u * PLANE_B, q5);
        }
        #undef LD4
    }
    __syncthreads();

    // per-image constants
    const int b = z / CH;
    const float dr = __uint_as_float(g_maxBits[b]) - __uint_as_float(g_minBits[b]);
    const float c1f = (0.01f * dr) * (0.01f * dr);
    const float c2f = (0.03f * dr) * (0.03f * dr);
    const ull C1 = rep2(c1f), C2 = rep2(c2f);
    const ull INV = rep2(1.f / 49.f), COVN = rep2(49.f / 48.f);
    const ull M1 = rep2(-1.f), TWO = rep2(2.f);

    // ---- stage B: f16x2 ring (10 rows/plane), packed f32x2 SSIM ----
    const unsigned cb = sb + (unsigned)lane * 4u;   // column pair 2*lane
    const int r0 = warp * 4;
    const bool ok0 = (x0 + 2 * lane) < OW;
    const bool ok1 = (x0 + 2 * lane + 1) < OW;

    unsigned W[4][4];
    #pragma unroll
    for (int p = 0; p < 4; p++) {
        const unsigned pb = cb + (unsigned)p * PLANE_B;
        unsigned v[10];
        #pragma unroll
        for (int k = 0; k < 10; k++) {
            const int rr = r0 + k;
            v[k] = lds1(pb + (unsigned)(rr * (STRH * 2)) + ((rr & 1) ? 16u : 0u));
        }
        unsigned s = hadd2u(hadd2u(hadd2u(v[0], v[1]), hadd2u(v[2], v[3])),
                            hadd2u(hadd2u(v[4], v[5]), v[6]));
        W[p][0] = s;
        #pragma unroll
        for (int j = 1; j < 4; j++) {
            s = hadd2u(s, v[6 + j]);
            s = hsub2u(s, v[j - 1]);
            W[p][j] = s;
        }
    }

    float accS = 0.f;
    #pragma unroll
    for (int j = 0; j < 4; j++) {
        const int oy = y0 + r0 + j;                 // uniform across warp
        if (oy < OW) {
            ull UX = mul2(h2f(W[0][j]), INV), UY = mul2(h2f(W[1][j]), INV);
            ull U34 = mul2(h2f(W[2][j]), INV), UXY = mul2(h2f(W[3][j]), INV);
            ull UX2 = mul2(UX, UX), UY2 = mul2(UY, UY), UXUY = mul2(UX, UY);
            ull SUMU2 = add2(UX2, UY2);
            ull VXY = mul2(fma2(UXUY, M1, UXY), COVN);
            ull VSUM = mul2(fma2(SUMU2, M1, U34), COVN);
            ull A1 = fma2(UXUY, TWO, C1);
            ull A2 = fma2(VXY, TWO, C2);
            ull B1 = add2(SUMU2, C1);
            ull B2 = add2(VSUM, C2);
            ull NUM = mul2(A1, A2);
            ull DEN = mul2(B1, B2);
            float n0, n1, d0, d1;
            unpk(NUM, n0, n1);
            unpk(DEN, d0, d1);
            if (ok0) accS += __fdividef(n0, d0);
            if (ok1) accS += __fdividef(n1, d1);
        }
    }

    // ---- block reduction -> one double atomic; last block finalizes ----
    #pragma unroll
    for (int o = 16; o; o >>= 1) accS += __shfl_down_sync(F8, accS, o);
    if (lane == 0) wsum[warp] = accS;
    __syncthreads();
    if (tid == 0) {
        float s = 0.f;
        #pragma unroll
        for (int i = 0; i < 8; i++) s += wsum[i];
        atomicAdd(&g_acc, (double)s);
        __threadfence();
        unsigned t = atomicAdd(&g_done, 1u);
        if (t == NBLOCKS - 1) {
            out[0] = (float)(1.0 - g_acc / ((double)BATCH * CH * OW * OW));
            g_acc = 0.0;
            g_done = 0u;
            #pragma unroll
            for (int i = 0; i < BATCH; i++) { g_minBits[i] = F8; g_maxBits[i] = 0u; }
        }
    }
}

extern "C" void kernel_launch(void* const* d_in, const int* in_sizes, int n_in,
                              void* d_out, int out_size) {
    const float* img1 = (const float*)d_in[0];
    const float* img2 = (const float*)d_in[1];

    const int smem_bytes = 4 * PLANE_B;  // 24,320 B
    cudaFuncSetAttribute(ssim_kernel, cudaFuncAttributeMaxDynamicSharedMemorySize,
                         smem_bytes);

    minmax_kernel<<<dim3(BATCH, 64), 256>>>(img2);
    dim3 grid(GX, GY, BATCH * CH);  // 8,16,96
    ssim_kernel<<<grid, 256, smem_bytes>>>(img1, img2, (float*)d_out);
}

// round 12
// speedup vs baseline: 1.0870x; 1.0870x over previous
#include <cuda_runtime.h>
#include <cuda_fp16.h>

#define HH 512
#define WW 512
#define OW 506
#define BATCH 32
#define CH 3
#define TX 64
#define TY 32
#define ITY 38          // TY + 6
#define STRH 80         // halves per hs row: 160B = 40 words == 8 mod 32
#define GX 8
#define GY 16
#define NBLOCKS (GX * GY * BATCH * CH)
#define PLANE_B (ITY * STRH * 2)   // bytes per plane = 6080

#define F8 0xFFFFFFFFu
__device__ unsigned g_minBits[BATCH] = {
    F8, F8, F8, F8, F8, F8, F8, F8, F8, F8, F8, F8, F8, F8, F8, F8,
    F8, F8, F8, F8, F8, F8, F8, F8, F8, F8, F8, F8, F8, F8, F8, F8};
__device__ unsigned g_maxBits[BATCH];
__device__ double g_acc;
__device__ unsigned g_done;

// ---------------- packed helpers ----------------
typedef unsigned long long ull;
__device__ __forceinline__ ull rep2(float f) {
    ull r; asm("mov.b64 %0,{%1,%1};" : "=l"(r) : "f"(f)); return r;
}
__device__ __forceinline__ ull add2(ull a, ull b) {
    ull d; asm("add.rn.f32x2 %0,%1,%2;" : "=l"(d) : "l"(a), "l"(b)); return d;
}
__device__ __forceinline__ ull mul2(ull a, ull b) {
    ull d; asm("mul.rn.f32x2 %0,%1,%2;" : "=l"(d) : "l"(a), "l"(b)); return d;
}
__device__ __forceinline__ ull fma2(ull a, ull b, ull c) {
    ull d; asm("fma.rn.f32x2 %0,%1,%2,%3;" : "=l"(d) : "l"(a), "l"(b), "l"(c)); return d;
}
__device__ __forceinline__ void unpk(ull v, float& a, float& b) {
    asm("mov.b64 {%0,%1},%2;" : "=f"(a), "=f"(b) : "l"(v));
}
__device__ __forceinline__ unsigned packh2(float lo, float hi) {
    unsigned r; asm("cvt.rn.f16x2.f32 %0,%1,%2;" : "=r"(r) : "f"(hi), "f"(lo));
    return r;
}
__device__ __forceinline__ ull h2f(unsigned h) {
    ull d;
    asm("{.reg .f16 l,u; .reg .f32 a,b; mov.b32 {l,u},%1;"
        " cvt.f32.f16 a,l; cvt.f32.f16 b,u; mov.b64 %0,{a,b};}"
        : "=l"(d) : "r"(h));
    return d;
}
__device__ __forceinline__ unsigned hadd2u(unsigned a, unsigned b) {
    unsigned d; asm("add.rn.f16x2 %0,%1,%2;" : "=r"(d) : "r"(a), "r"(b)); return d;
}
__device__ __forceinline__ unsigned hsub2u(unsigned a, unsigned b) {
    unsigned d; asm("sub.rn.f16x2 %0,%1,%2;" : "=r"(d) : "r"(a), "r"(b)); return d;
}
__device__ __forceinline__ unsigned lds1(unsigned a) {
    unsigned v; asm volatile("ld.shared.b32 %0,[%1];" : "=r"(v) : "r"(a)); return v;
}
__device__ __forceinline__ void sts4u(unsigned a, uint4 v) {
    asm volatile("st.shared.v4.b32 [%0],{%1,%2,%3,%4};"
                 :: "r"(a), "r"(v.x), "r"(v.y), "r"(v.z), "r"(v.w) : "memory");
}

// Per-image min/max of img2 (values >= 0 -> uint ordering == float ordering).
__global__ void minmax_kernel(const float* __restrict__ img2) {
    int b = blockIdx.x;
    const float4* p = (const float4*)(img2 + (size_t)b * (CH * HH * WW));
    const int n4 = CH * HH * WW / 4;           // 196608
    const int stride = gridDim.y * blockDim.x; // 24576
    unsigned lo = F8, hi = 0u;
    int i = blockIdx.y * blockDim.x + threadIdx.x;
    for (; i + 3 * stride < n4; i += 4 * stride) {
        float4 v0 = p[i];
        float4 v1 = p[i + stride];
        float4 v2 = p[i + 2 * stride];
        float4 v3 = p[i + 3 * stride];
        #define MM(v) { \
            unsigned a0 = __float_as_uint((v).x), a1 = __float_as_uint((v).y); \
            unsigned a2 = __float_as_uint((v).z), a3 = __float_as_uint((v).w); \
            lo = min(lo, min(min(a0, a1), min(a2, a3))); \
            hi = max(hi, max(max(a0, a1), max(a2, a3))); }
        MM(v0) MM(v1) MM(v2) MM(v3)
    }
    for (; i < n4; i += stride) { float4 v = p[i]; MM(v) }
    #undef MM
    #pragma unroll
    for (int o = 16; o; o >>= 1) {
        lo = min(lo, __shfl_down_sync(F8, lo, o));
        hi = max(hi, __shfl_down_sync(F8, hi, o));
    }
    __shared__ unsigned slo[8], shi[8];
    int lane = threadIdx.x & 31, w = threadIdx.x >> 5;
    if (lane == 0) { slo[w] = lo; shi[w] = hi; }
    __syncthreads();
    if (threadIdx.x == 0) {
        #pragma unroll
        for (int k = 1; k < 8; k++) { lo = min(lo, slo[k]); hi = max(hi, shi[k]); }
        atomicMin(&g_minBits[b], lo);
        atomicMax(&g_maxBits[b], hi);
    }
}

// One 64x32 output tile per block. 4 fp16 SMEM planes: sum(x), sum(y),
// sum(x^2+y^2), sum(xy). Row pitch 40 words == 8 mod 32 -> conflict-free
// STS.128 and 1-wavefront LDS.32. Stage A: 8-col items, phased float4
// loads. Stage B: f16x2 ring + packed f32x2 SSIM, fused pair division.
// 6 blocks/SM (reg cap 42).
__global__ __launch_bounds__(256, 6) void ssim_kernel(const float* __restrict__ X,
                                                      const float* __restrict__ Y,
                                                      float* __restrict__ out) {
    extern __shared__ char smraw[];
    __shared__ float wsum[8];

    const int z = blockIdx.z;
    const size_t base = (size_t)z * (HH * WW);
    const int x0 = blockIdx.x * TX;
    const int y0 = blockIdx.y * TY;
    const int tid = threadIdx.x, lane = tid & 31, warp = tid >> 5;
    const unsigned sb = (unsigned)__cvta_generic_to_shared(smraw);

    // ---- stage A: horizontal 7-sums, 8 output cols per item ----
    for (int item = tid; item < ITY * 8; item += 256) {
        const int r = item >> 3;
        const int c0 = (item & 7) * 8;
        const int iy = y0 + r;
        const float* px = X + base + (size_t)iy * WW;
        const float* py = Y + base + (size_t)iy * WW;
        const bool yok = iy < HH;

        float ax[16], ay[16];
        #pragma unroll
        for (int k = 0; k < 3; k++) {
            const int col = x0 + c0 + 4 * k;
            const bool ok = yok && (col <= WW - 4);
            float4 vx = ok ? *(const float4*)(px + col) : make_float4(0, 0, 0, 0);
            float4 vy = ok ? *(const float4*)(py + col) : make_float4(0, 0, 0, 0);
            ax[4 * k + 0] = vx.x; ax[4 * k + 1] = vx.y;
            ax[4 * k + 2] = vx.z; ax[4 * k + 3] = vx.w;
            ay[4 * k + 0] = vy.x; ay[4 * k + 1] = vy.y;
            ay[4 * k + 2] = vy.z; ay[4 * k + 3] = vy.w;
        }

        float s1 = 0.f, s2 = 0.f, s34 = 0.f, s5 = 0.f;
        #pragma unroll
        for (int k = 0; k < 7; k++) {
            s1 += ax[k]; s2 += ay[k];
            s34 += ax[k] * ax[k] + ay[k] * ay[k];
            s5 += ax[k] * ay[k];
        }

        uint4 q1, q2, q34, q5;
        float l1 = s1, l2 = s2, l34 = s34, l5 = s5;
        #pragma unroll
        for (int cc = 1; cc < 8; cc++) {
            if (cc == 4) {
                const int col = x0 + c0 + 12;
                const bool ok = yok && (col <= WW - 4);
                float4 vx = ok ? *(const float4*)(px + col) : make_float4(0, 0, 0, 0);
                float4 vy = ok ? *(const float4*)(py + col) : make_float4(0, 0, 0, 0);
                ax[12] = vx.x; ax[13] = vx.y; ax[14] = vx.z; ax[15] = vx.w;
                ay[12] = vy.x; ay[13] = vy.y; ay[14] = vy.z; ay[15] = vy.w;
            }
            const float xn = ax[6 + cc], yn = ay[6 + cc];
            const float xo = ax[cc - 1], yo = ay[cc - 1];
            s1 += xn - xo;
            s2 += yn - yo;
            s34 += xn * xn + yn * yn - xo * xo - yo * yo;
            s5 += xn * yn - xo * yo;
            if (cc & 1) {
                const int q = cc >> 1;
                ((unsigned*)&q1)[q] = packh2(l1, s1);
                ((unsigned*)&q2)[q] = packh2(l2, s2);
                ((unsigned*)&q34)[q] = packh2(l34, s34);
                ((unsigned*)&q5)[q] = packh2(l5, s5);
            } else {
                l1 = s1; l2 = s2; l34 = s34; l5 = s5;
            }
        }

        const unsigned rowb = sb + (unsigned)(r * (STRH * 2) + c0 * 2);
        sts4u(rowb + 0u * PLANE_B, q1);
        sts4u(rowb + 1u * PLANE_B, q2);
        sts4u(rowb + 2u * PLANE_B, q34);
        sts4u(rowb + 3u * PLANE_B, q5);
    }
    __syncthreads();

    // per-image constants
    const int b = z / CH;
    const float dr = __uint_as_float(g_maxBits[b]) - __uint_as_float(g_minBits[b]);
    const float c1f = (0.01f * dr) * (0.01f * dr);
    const float c2f = (0.03f * dr) * (0.03f * dr);
    const ull C1 = rep2(c1f), C2 = rep2(c2f);
    const ull INV = rep2(1.f / 49.f), COVN = rep2(49.f / 48.f);
    const ull M1 = rep2(-1.f), TWO = rep2(2.f);

    // ---- stage B: f16x2 ring (10 rows/plane, loaded once), windows in f16,
    //      converted per output row to packed f32x2 for SSIM ----
    const unsigned cb = sb + (unsigned)lane * 4u;   // column pair 2*lane
    const int r0 = warp * 4;
    // OW is even and pairs are aligned -> both pair columns share validity.
    const bool okx = (x0 + 2 * lane) < OW;

    unsigned W[4][4];
    #pragma unroll
    for (int p = 0; p < 4; p++) {
        const unsigned pb = cb + (unsigned)p * PLANE_B;
        unsigned v[10];
        #pragma unroll
        for (int k = 0; k < 10; k++)
            v[k] = lds1(pb + (unsigned)(r0 + k) * (STRH * 2));
        unsigned s = hadd2u(hadd2u(hadd2u(v[0], v[1]), hadd2u(v[2], v[3])),
                            hadd2u(hadd2u(v[4], v[5]), v[6]));
        W[p][0] = s;
        #pragma unroll
        for (int j = 1; j < 4; j++) {
            s = hadd2u(s, v[6 + j]);
            s = hsub2u(s, v[j - 1]);
            W[p][j] = s;
        }
    }

    float accS = 0.f;
    #pragma unroll
    for (int j = 0; j < 4; j++) {
        const int oy = y0 + r0 + j;                 // uniform across warp
        if (okx && oy < OW) {
            ull UX = mul2(h2f(W[0][j]), INV), UY = mul2(h2f(W[1][j]), INV);
            ull U34 = mul2(h2f(W[2][j]), INV), UXY = mul2(h2f(W[3][j]), INV);
            ull UX2 = mul2(UX, UX), UY2 = mul2(UY, UY), UXUY = mul2(UX, UY);
            ull SUMU2 = add2(UX2, UY2);
            ull VXY = mul2(fma2(UXUY, M1, UXY), COVN);
            ull VSUM = mul2(fma2(SUMU2, M1, U34), COVN);
            ull A1 = fma2(UXUY, TWO, C1);
            ull A2 = fma2(VXY, TWO, C2);
            ull B1 = add2(SUMU2, C1);
            ull B2 = add2(VSUM, C2);
            ull NUM = mul2(A1, A2);
            ull DEN = mul2(B1, B2);
            float n0, n1, d0, d1;
            unpk(NUM, n0, n1);
            unpk(DEN, d0, d1);
            // n0/d0 + n1/d1 with a single division
            accS += __fdividef(n0 * d1 + n1 * d0, d0 * d1);
        }
    }

    // ---- block reduction -> one double atomic; last block finalizes ----
    #pragma unroll
    for (int o = 16; o; o >>= 1) accS += __shfl_down_sync(F8, accS, o);
    if (lane == 0) wsum[warp] = accS;
    __syncthreads();
    if (tid == 0) {
        float s = 0.f;
        #pragma unroll
        for (int i = 0; i < 8; i++) s += wsum[i];
        atomicAdd(&g_acc, (double)s);
        __threadfence();
        unsigned t = atomicAdd(&g_done, 1u);
        if (t == NBLOCKS - 1) {
            out[0] = (float)(1.0 - g_acc / ((double)BATCH * CH * OW * OW));
            g_acc = 0.0;
            g_done = 0u;
            #pragma unroll
            for (int i = 0; i < BATCH; i++) { g_minBits[i] = F8; g_maxBits[i] = 0u; }
        }
    }
}

extern "C" void kernel_launch(void* const* d_in, const int* in_sizes, int n_in,
                              void* d_out, int out_size) {
    const float* img1 = (const float*)d_in[0];
    const float* img2 = (const float*)d_in[1];

    const int smem_bytes = 4 * PLANE_B;  // 24,320 B
    cudaFuncSetAttribute(ssim_kernel, cudaFuncAttributeMaxDynamicSharedMemorySize,
                         smem_bytes);

    minmax_kernel<<<dim3(BATCH, 96), 256>>>(img2);
    dim3 grid(GX, GY, BATCH * CH);  // 8,16,96
    ssim_kernel<<<grid, 256, smem_bytes>>>(img1, img2, (float*)d_out);
}